// round 12
// baseline (speedup 1.0000x reference)
#include <cuda_runtime.h>

#define NN 50000
#define EE 800000
#define DD 64
#define NB 196   // (NN + 255) / 256 scan blocks
#define RP 132   // sI row pitch in floats (128 + 4 pad)

// Scratch (device globals — allocation-free per harness rules)
__device__ __align__(16) float g_h[NN * DD];     // layer-1 output
__device__ int g_src32[EE];
__device__ int g_dst32[EE];
__device__ int g_deg[NN];       // degree histogram; consumed (decremented to 0) by fill
__device__ int g_loc[NN];       // per-element exclusive scan within its block
__device__ int g_bsum[NB];      // per-block degree sums
__device__ int g_bbase[NB];     // exclusive scan of block sums
__device__ int g_csr_src[EE];
__device__ int g_scan_count;    // zero-init; reset by scan itself each run

__device__ __forceinline__ int node_off(int n) {
    return g_loc[n] + g_bbase[n >> 8];
}

// ---------------------------------------------------------------------------
// Kernel 1: normalize indices to int32 + integer degree histogram.
// Dtype self-detect per block: int64 layout => first 64 odd 32-bit words all
// zero (L2-broadcast probe, ~free).
// ---------------------------------------------------------------------------
__global__ __launch_bounds__(256) void convert_kernel(const void* __restrict__ ei) {
    const int* ei32 = (const int*)ei;
    __shared__ int s_is64;
    if (threadIdx.x == 0) s_is64 = 1;
    __syncthreads();
    if (threadIdx.x < 64 && ei32[2 * threadIdx.x + 1] != 0) atomicExch(&s_is64, 0);
    __syncthreads();

    int e = blockIdx.x * blockDim.x + threadIdx.x;
    if (e >= EE) return;
    int s, d;
    if (s_is64) {
        const long long* p = (const long long*)ei;
        s = (int)p[e];
        d = (int)p[EE + e];
    } else {
        const int* p = (const int*)ei;
        s = p[e];
        d = p[EE + e];
    }
    s = min(max(s, 0), NN - 1);
    d = min(max(d, 0), NN - 1);
    g_src32[e] = s;
    g_dst32[e] = d;
    atomicAdd(&g_deg[d], 1);
}

// ---------------------------------------------------------------------------
// Kernel 2: single-pass exclusive scan. Every block scans its 256 degrees
// (g_loc + g_bsum); the LAST block to finish additionally scans the 196
// block sums into g_bbase and resets the arrival counter (graph-replayable).
// ---------------------------------------------------------------------------
__global__ __launch_bounds__(256) void scan_kernel() {
    __shared__ int sh[256];
    __shared__ int is_last;
    int tid = threadIdx.x;
    int i = blockIdx.x * 256 + tid;
    int v = (i < NN) ? g_deg[i] : 0;
    sh[tid] = v;
    __syncthreads();
    #pragma unroll
    for (int d = 1; d < 256; d <<= 1) {
        int t = (tid >= d) ? sh[tid - d] : 0;
        __syncthreads();
        sh[tid] += t;
        __syncthreads();
    }
    if (i < NN) g_loc[i] = sh[tid] - v;           // exclusive within block
    if (tid == 255) g_bsum[blockIdx.x] = sh[255]; // block total

    __threadfence();
    if (tid == 0) is_last = (atomicAdd(&g_scan_count, 1) == NB - 1);
    __syncthreads();

    if (is_last) {
        int v2 = (tid < NB) ? g_bsum[tid] : 0;
        sh[tid] = v2;
        __syncthreads();
        #pragma unroll
        for (int d = 1; d < 256; d <<= 1) {
            int t = (tid >= d) ? sh[tid - d] : 0;
            __syncthreads();
            sh[tid] += t;
            __syncthreads();
        }
        if (tid < NB) g_bbase[tid] = sh[tid] - v2;
        if (tid == 0) g_scan_count = 0;           // reset for next graph replay
    }
}

// ---------------------------------------------------------------------------
// Kernel 3: CSR fill. Slot = off(d) + (atomicSub(deg)-1); g_deg drains to 0.
// ---------------------------------------------------------------------------
__global__ __launch_bounds__(256) void fill_kernel() {
    int e = blockIdx.x * blockDim.x + threadIdx.x;
    if (e >= EE) return;
    int d = g_dst32[e];
    int off = node_off(d);
    int slot = atomicSub(&g_deg[d], 1) - 1;
    g_csr_src[off + slot] = g_src32[e];
}

// ---------------------------------------------------------------------------
// Kernel 4/5: FUSED aggregation + MLP, 512 threads/block (16 warps).
// Same 66KB smem => 3 blocks/SM resident => 48 warps/SM (75% occ) for
// latency hiding (R11 profile: occ 33%, issue 40%, nothing saturated).
// Gather: 32 half-warps x 1 node-pair (A,B interleaved, 2-edge unroll
// => 4 independent row-load streams per half-warp).
// Compute: 64x64 tile, 2x4 micro-tile/thread.
// ---------------------------------------------------------------------------
#define MLP_SMEM_BYTES ((2 * DD * DD + 64 * RP + DD) * 4)

#define ACC4(a, v) { a.x += v.x; a.y += v.y; a.z += v.z; a.w += v.w; }

template <int LAYER>
__global__ __launch_bounds__(512) void fused_kernel(
    const float* __restrict__ xext,
    const float* __restrict__ Wl,
    const float* __restrict__ bl,
    const float* __restrict__ Wr,
    float* __restrict__ outext)
{
    const float* xin = (LAYER == 1) ? xext : g_h;
    float*       out = (LAYER == 1) ? g_h : outext;

    extern __shared__ float smem[];
    float* sW = smem;                 // 8192 floats: sW[k*64 + j]
    float* sI = smem + 2 * DD * DD;   // 64 * RP floats: sI[node*RP + k]
    float* sB = sI + 64 * RP;         // 64 floats

    // Stage combined weights, k-major transposed
    for (int t = threadIdx.x; t < DD * DD; t += 512) {
        int j = t >> 6, k = t & 63;
        sW[k * DD + j]        = Wl[t];
        sW[(DD + k) * DD + j] = Wr[t];
    }
    if (threadIdx.x < DD) sB[threadIdx.x] = bl[threadIdx.x];

    const int hw = threadIdx.x >> 4;        // half-warp id 0..31
    const int fl = threadIdx.x & 15;        // feature float4 index
    const int fo = fl << 2;                 // float offset within row

    const int ty = threadIdx.x >> 4;        // 0..31 -> node pair (compute)
    const int tx = threadIdx.x & 15;        // 0..15 -> output group
    const int n0 = ty << 1;
    const int j0 = tx << 2;
    const int ngroups = (NN + 63) / 64;     // 782

    for (int g = blockIdx.x; g < ngroups; g += gridDim.x) {
        int base = g << 6;
        __syncthreads();   // smem reuse from previous group

        // ---- Gather + stage: each half-warp owns nodes 2*hw, 2*hw+1 ----
        {
            int nodeA = hw << 1;
            int nodeB = nodeA + 1;
            int niA = base + nodeA;
            int niB = base + nodeB;
            int begA = 0, lenA = 0, begB = 0, lenB = 0;
            if (niA < NN) {
                begA = node_off(niA);
                lenA = ((niA + 1 < NN) ? node_off(niA + 1) : EE) - begA;
            }
            if (niB < NN) {
                begB = node_off(niB);
                lenB = ((niB + 1 < NN) ? node_off(niB + 1) : EE) - begB;
            }

            float4 aA0 = make_float4(0.f, 0.f, 0.f, 0.f);
            float4 aA1 = make_float4(0.f, 0.f, 0.f, 0.f);
            float4 aB0 = make_float4(0.f, 0.f, 0.f, 0.f);
            float4 aB1 = make_float4(0.f, 0.f, 0.f, 0.f);

            int m = max(lenA, lenB);
            #pragma unroll 1
            for (int i = 0; i < m; i += 2) {
                int sA0 = (i     < lenA) ? g_csr_src[begA + i]     : -1;
                int sA1 = (i + 1 < lenA) ? g_csr_src[begA + i + 1] : -1;
                int sB0 = (i     < lenB) ? g_csr_src[begB + i]     : -1;
                int sB1 = (i + 1 < lenB) ? g_csr_src[begB + i + 1] : -1;
                if (sA0 >= 0) { float4 v = *reinterpret_cast<const float4*>(xin + (size_t)sA0 * DD + fo); ACC4(aA0, v); }
                if (sA1 >= 0) { float4 v = *reinterpret_cast<const float4*>(xin + (size_t)sA1 * DD + fo); ACC4(aA1, v); }
                if (sB0 >= 0) { float4 v = *reinterpret_cast<const float4*>(xin + (size_t)sB0 * DD + fo); ACC4(aB0, v); }
                if (sB1 >= 0) { float4 v = *reinterpret_cast<const float4*>(xin + (size_t)sB1 * DD + fo); ACC4(aB1, v); }
            }

            float invA = 1.0f / (float)max(lenA, 1);
            float invB = 1.0f / (float)max(lenB, 1);
            aA0.x = (aA0.x + aA1.x) * invA;  aA0.y = (aA0.y + aA1.y) * invA;
            aA0.z = (aA0.z + aA1.z) * invA;  aA0.w = (aA0.w + aA1.w) * invA;
            aB0.x = (aB0.x + aB1.x) * invB;  aB0.y = (aB0.y + aB1.y) * invB;
            aB0.z = (aB0.z + aB1.z) * invB;  aB0.w = (aB0.w + aB1.w) * invB;
            *reinterpret_cast<float4*>(sI + nodeA * RP + fo) = aA0;
            *reinterpret_cast<float4*>(sI + nodeB * RP + fo) = aB0;

            float4 xvA = make_float4(0.f, 0.f, 0.f, 0.f);
            float4 xvB = make_float4(0.f, 0.f, 0.f, 0.f);
            if (niA < NN) xvA = *reinterpret_cast<const float4*>(xin + (size_t)niA * DD + fo);
            if (niB < NN) xvB = *reinterpret_cast<const float4*>(xin + (size_t)niB * DD + fo);
            *reinterpret_cast<float4*>(sI + nodeA * RP + DD + fo) = xvA;
            *reinterpret_cast<float4*>(sI + nodeB * RP + DD + fo) = xvB;
        }
        __syncthreads();

        // ---- Compute: 2x4 micro-tile per thread ----
        float acc[2][4];
        #pragma unroll
        for (int i = 0; i < 2; i++)
            #pragma unroll
            for (int j = 0; j < 4; j++) acc[i][j] = 0.f;

        const float* r0 = sI + (n0 + 0) * RP;
        const float* r1 = sI + (n0 + 1) * RP;

        #pragma unroll 8
        for (int k = 0; k < 2 * DD; k++) {
            float4 w = *reinterpret_cast<const float4*>(sW + k * DD + j0);
            float a0v = r0[k], a1v = r1[k];
            acc[0][0] += a0v * w.x; acc[0][1] += a0v * w.y; acc[0][2] += a0v * w.z; acc[0][3] += a0v * w.w;
            acc[1][0] += a1v * w.x; acc[1][1] += a1v * w.y; acc[1][2] += a1v * w.z; acc[1][3] += a1v * w.w;
        }

        float4 b4 = *reinterpret_cast<const float4*>(sB + j0);
        #pragma unroll
        for (int i = 0; i < 2; i++) {
            int ni = base + n0 + i;
            if (ni < NN) {
                float4 o;
                o.x = acc[i][0] + b4.x;
                o.y = acc[i][1] + b4.y;
                o.z = acc[i][2] + b4.z;
                o.w = acc[i][3] + b4.w;
                if (LAYER == 1) {
                    o.x = tanhf(o.x); o.y = tanhf(o.y);
                    o.z = tanhf(o.z); o.w = tanhf(o.w);
                }
                *reinterpret_cast<float4*>(out + (size_t)ni * DD + j0) = o;
            }
        }
    }
}

// ---------------------------------------------------------------------------
// Launch
// ---------------------------------------------------------------------------
extern "C" void kernel_launch(void* const* d_in, const int* in_sizes, int n_in,
                              void* d_out, int out_size)
{
    const float* x    = (const float*)d_in[0];
    const void*  ei   = d_in[1];
    const float* Wl1  = (const float*)d_in[2];
    const float* bl1  = (const float*)d_in[3];
    const float* Wr1  = (const float*)d_in[4];
    const float* Wl2  = (const float*)d_in[5];
    const float* bl2  = (const float*)d_in[6];
    const float* Wr2  = (const float*)d_in[7];
    float*       out  = (float*)d_out;

    // One-time immediate-API setup (capture-safe, no allocation)
    static void* deg_addr = nullptr;
    if (!deg_addr) {
        cudaGetSymbolAddress(&deg_addr, g_deg);
        cudaFuncSetAttribute(fused_kernel<1>,
            cudaFuncAttributeMaxDynamicSharedMemorySize, MLP_SMEM_BYTES);
        cudaFuncSetAttribute(fused_kernel<2>,
            cudaFuncAttributeMaxDynamicSharedMemorySize, MLP_SMEM_BYTES);
    }

    const int eb = (EE + 255) / 256;   // edge-parallel blocks
    const int fb = 391;                // 782 groups = exactly 2 per block, one wave

    cudaMemsetAsync(deg_addr, 0, NN * sizeof(int));
    convert_kernel<<<eb, 256>>>(ei);
    scan_kernel<<<NB, 256>>>();
    fill_kernel<<<eb, 256>>>();
    fused_kernel<1><<<fb, 512, MLP_SMEM_BYTES>>>(x, Wl1, bl1, Wr1, nullptr);
    fused_kernel<2><<<fb, 512, MLP_SMEM_BYTES>>>(nullptr, Wl2, bl2, Wr2, out);
}

// round 13
// speedup vs baseline: 1.0331x; 1.0331x over previous
#include <cuda_runtime.h>
#include <cuda_fp16.h>

#define NN 50000
#define EE 800000
#define DD 64
#define NB 196   // (NN + 255) / 256 scan blocks
#define RP 132   // sI row pitch in floats (128 + 4 pad)

// Scratch (device globals — allocation-free per harness rules)
__device__ __align__(16) float g_h[NN * DD];       // layer-1 output (fp32, self-term)
__device__ __align__(16) __half2 g_xh[NN * DD / 2]; // x as fp16 (neighbor gather)
__device__ __align__(16) __half2 g_hh[NN * DD / 2]; // h as fp16 (neighbor gather)
__device__ int g_src32[EE];
__device__ int g_dst32[EE];
__device__ int g_deg[NN];       // degree histogram; consumed (decremented to 0) by fill
__device__ int g_loc[NN];       // per-element exclusive scan within its block
__device__ int g_bsum[NB];      // per-block degree sums
__device__ int g_bbase[NB];     // exclusive scan of block sums
__device__ int g_csr_src[EE];
__device__ int g_scan_count;    // zero-init; reset by scan itself each run

__device__ __forceinline__ int node_off(int n) {
    return g_loc[n] + g_bbase[n >> 8];
}

// ---------------------------------------------------------------------------
// Kernel 0b: convert x -> fp16 (neighbor-gather copy)
// ---------------------------------------------------------------------------
__global__ __launch_bounds__(256) void tohalf_kernel(const float* __restrict__ x) {
    int i = blockIdx.x * 256 + threadIdx.x;
    if (i < NN * DD / 2) {
        float2 v = reinterpret_cast<const float2*>(x)[i];
        g_xh[i] = __floats2half2_rn(v.x, v.y);
    }
}

// ---------------------------------------------------------------------------
// Kernel 1: normalize indices to int32 + integer degree histogram.
// Dtype self-detect per block (int64 => first 64 odd 32-bit words all zero).
// ---------------------------------------------------------------------------
__global__ __launch_bounds__(256) void convert_kernel(const void* __restrict__ ei) {
    const int* ei32 = (const int*)ei;
    __shared__ int s_is64;
    if (threadIdx.x == 0) s_is64 = 1;
    __syncthreads();
    if (threadIdx.x < 64 && ei32[2 * threadIdx.x + 1] != 0) atomicExch(&s_is64, 0);
    __syncthreads();

    int e = blockIdx.x * blockDim.x + threadIdx.x;
    if (e >= EE) return;
    int s, d;
    if (s_is64) {
        const long long* p = (const long long*)ei;
        s = (int)p[e];
        d = (int)p[EE + e];
    } else {
        const int* p = (const int*)ei;
        s = p[e];
        d = p[EE + e];
    }
    s = min(max(s, 0), NN - 1);
    d = min(max(d, 0), NN - 1);
    g_src32[e] = s;
    g_dst32[e] = d;
    atomicAdd(&g_deg[d], 1);
}

// ---------------------------------------------------------------------------
// Kernel 2: single-pass exclusive scan (decoupled last-block).
// ---------------------------------------------------------------------------
__global__ __launch_bounds__(256) void scan_kernel() {
    __shared__ int sh[256];
    __shared__ int is_last;
    int tid = threadIdx.x;
    int i = blockIdx.x * 256 + tid;
    int v = (i < NN) ? g_deg[i] : 0;
    sh[tid] = v;
    __syncthreads();
    #pragma unroll
    for (int d = 1; d < 256; d <<= 1) {
        int t = (tid >= d) ? sh[tid - d] : 0;
        __syncthreads();
        sh[tid] += t;
        __syncthreads();
    }
    if (i < NN) g_loc[i] = sh[tid] - v;
    if (tid == 255) g_bsum[blockIdx.x] = sh[255];

    __threadfence();
    if (tid == 0) is_last = (atomicAdd(&g_scan_count, 1) == NB - 1);
    __syncthreads();

    if (is_last) {
        int v2 = (tid < NB) ? g_bsum[tid] : 0;
        sh[tid] = v2;
        __syncthreads();
        #pragma unroll
        for (int d = 1; d < 256; d <<= 1) {
            int t = (tid >= d) ? sh[tid - d] : 0;
            __syncthreads();
            sh[tid] += t;
            __syncthreads();
        }
        if (tid < NB) g_bbase[tid] = sh[tid] - v2;
        if (tid == 0) g_scan_count = 0;
    }
}

// ---------------------------------------------------------------------------
// Kernel 3: CSR fill. Slot = off(d) + (atomicSub(deg)-1); g_deg drains to 0.
// ---------------------------------------------------------------------------
__global__ __launch_bounds__(256) void fill_kernel() {
    int e = blockIdx.x * blockDim.x + threadIdx.x;
    if (e >= EE) return;
    int d = g_dst32[e];
    int off = node_off(d);
    int slot = atomicSub(&g_deg[d], 1) - 1;
    g_csr_src[off + slot] = g_src32[e];
}

// ---------------------------------------------------------------------------
// Kernel 4/5: FUSED aggregation + MLP (256 threads, R11 structure).
// Neighbor rows are fp16 (128B/row, one L1 line): uint2 per lane, converted
// to fp32 on accumulate. Self-term and all GEMM math remain fp32.
// Layer 1 epilogue writes h in fp32 (self-term) AND fp16 (gather copy).
// ---------------------------------------------------------------------------
#define MLP_SMEM_BYTES ((2 * DD * DD + 64 * RP + DD) * 4)

#define ACCH(a, u) {                                            \
    __half2 _h0 = *reinterpret_cast<const __half2*>(&(u).x);    \
    __half2 _h1 = *reinterpret_cast<const __half2*>(&(u).y);    \
    float2 _f0 = __half22float2(_h0);                           \
    float2 _f1 = __half22float2(_h1);                           \
    (a).x += _f0.x; (a).y += _f0.y; (a).z += _f1.x; (a).w += _f1.y; }

template <int LAYER>
__global__ __launch_bounds__(256) void fused_kernel(
    const float* __restrict__ xext,
    const float* __restrict__ Wl,
    const float* __restrict__ bl,
    const float* __restrict__ Wr,
    float* __restrict__ outext)
{
    const float*   self = (LAYER == 1) ? xext : g_h;   // fp32 self rows
    const __half2* nb   = (LAYER == 1) ? g_xh : g_hh;  // fp16 neighbor rows
    float*         out  = (LAYER == 1) ? g_h : outext;

    extern __shared__ float smem[];
    float* sW = smem;                 // 8192 floats: sW[k*64 + j]
    float* sI = smem + 2 * DD * DD;   // 64 * RP floats: sI[node*RP + k]
    float* sB = sI + 64 * RP;         // 64 floats

    for (int t = threadIdx.x; t < DD * DD; t += 256) {
        int j = t >> 6, k = t & 63;
        sW[k * DD + j]        = Wl[t];
        sW[(DD + k) * DD + j] = Wr[t];
    }
    if (threadIdx.x < DD) sB[threadIdx.x] = bl[threadIdx.x];

    const int wid  = threadIdx.x >> 5;      // warp 0..7
    const int lane = threadIdx.x & 31;
    const int half = lane >> 4;             // 0/1
    const int fl   = lane & 15;             // feature float4 index
    const int fo   = fl << 2;               // float offset within row

    const int ty = threadIdx.x >> 4;        // 0..15 -> node group (compute)
    const int tx = threadIdx.x & 15;        // 0..15 -> output group
    const int n0 = ty << 2;
    const int j0 = tx << 2;
    const int ngroups = (NN + 63) / 64;     // 782

    for (int g = blockIdx.x; g < ngroups; g += gridDim.x) {
        int base = g << 6;
        __syncthreads();

        // ---- Gather + stage: half-warp owns 4 nodes, processed as 2 pairs ----
        #pragma unroll 1
        for (int pp = 0; pp < 2; pp++) {
            int nodeA = (wid << 3) + (pp << 2) + half;  // 0..63
            int nodeB = nodeA + 2;
            int niA = base + nodeA;
            int niB = base + nodeB;
            int begA = 0, lenA = 0, begB = 0, lenB = 0;
            if (niA < NN) {
                begA = node_off(niA);
                lenA = ((niA + 1 < NN) ? node_off(niA + 1) : EE) - begA;
            }
            if (niB < NN) {
                begB = node_off(niB);
                lenB = ((niB + 1 < NN) ? node_off(niB + 1) : EE) - begB;
            }

            float4 aA0 = make_float4(0.f, 0.f, 0.f, 0.f);
            float4 aA1 = make_float4(0.f, 0.f, 0.f, 0.f);
            float4 aB0 = make_float4(0.f, 0.f, 0.f, 0.f);
            float4 aB1 = make_float4(0.f, 0.f, 0.f, 0.f);

            int m = max(lenA, lenB);
            #pragma unroll 1
            for (int i = 0; i < m; i += 2) {
                int sA0 = (i     < lenA) ? g_csr_src[begA + i]     : -1;
                int sA1 = (i + 1 < lenA) ? g_csr_src[begA + i + 1] : -1;
                int sB0 = (i     < lenB) ? g_csr_src[begB + i]     : -1;
                int sB1 = (i + 1 < lenB) ? g_csr_src[begB + i + 1] : -1;
                if (sA0 >= 0) { uint2 u = reinterpret_cast<const uint2*>(nb + (size_t)sA0 * 32)[fl]; ACCH(aA0, u); }
                if (sA1 >= 0) { uint2 u = reinterpret_cast<const uint2*>(nb + (size_t)sA1 * 32)[fl]; ACCH(aA1, u); }
                if (sB0 >= 0) { uint2 u = reinterpret_cast<const uint2*>(nb + (size_t)sB0 * 32)[fl]; ACCH(aB0, u); }
                if (sB1 >= 0) { uint2 u = reinterpret_cast<const uint2*>(nb + (size_t)sB1 * 32)[fl]; ACCH(aB1, u); }
            }

            float invA = 1.0f / (float)max(lenA, 1);
            float invB = 1.0f / (float)max(lenB, 1);
            aA0.x = (aA0.x + aA1.x) * invA;  aA0.y = (aA0.y + aA1.y) * invA;
            aA0.z = (aA0.z + aA1.z) * invA;  aA0.w = (aA0.w + aA1.w) * invA;
            aB0.x = (aB0.x + aB1.x) * invB;  aB0.y = (aB0.y + aB1.y) * invB;
            aB0.z = (aB0.z + aB1.z) * invB;  aB0.w = (aB0.w + aB1.w) * invB;
            *reinterpret_cast<float4*>(sI + nodeA * RP + fo) = aA0;
            *reinterpret_cast<float4*>(sI + nodeB * RP + fo) = aB0;

            float4 xvA = make_float4(0.f, 0.f, 0.f, 0.f);
            float4 xvB = make_float4(0.f, 0.f, 0.f, 0.f);
            if (niA < NN) xvA = *reinterpret_cast<const float4*>(self + (size_t)niA * DD + fo);
            if (niB < NN) xvB = *reinterpret_cast<const float4*>(self + (size_t)niB * DD + fo);
            *reinterpret_cast<float4*>(sI + nodeA * RP + DD + fo) = xvA;
            *reinterpret_cast<float4*>(sI + nodeB * RP + DD + fo) = xvB;
        }
        __syncthreads();

        // ---- Compute: 4x4 micro-tile per thread (fp32) ----
        float acc[4][4];
        #pragma unroll
        for (int i = 0; i < 4; i++)
            #pragma unroll
            for (int j = 0; j < 4; j++) acc[i][j] = 0.f;

        const float* r0 = sI + (n0 + 0) * RP;
        const float* r1 = sI + (n0 + 1) * RP;
        const float* r2 = sI + (n0 + 2) * RP;
        const float* r3 = sI + (n0 + 3) * RP;

        #pragma unroll 4
        for (int k = 0; k < 2 * DD; k++) {
            float4 w = *reinterpret_cast<const float4*>(sW + k * DD + j0);
            float a0v = r0[k], a1v = r1[k], a2v = r2[k], a3v = r3[k];
            acc[0][0] += a0v * w.x; acc[0][1] += a0v * w.y; acc[0][2] += a0v * w.z; acc[0][3] += a0v * w.w;
            acc[1][0] += a1v * w.x; acc[1][1] += a1v * w.y; acc[1][2] += a1v * w.z; acc[1][3] += a1v * w.w;
            acc[2][0] += a2v * w.x; acc[2][1] += a2v * w.y; acc[2][2] += a2v * w.z; acc[2][3] += a2v * w.w;
            acc[3][0] += a3v * w.x; acc[3][1] += a3v * w.y; acc[3][2] += a3v * w.z; acc[3][3] += a3v * w.w;
        }

        float4 b4 = *reinterpret_cast<const float4*>(sB + j0);
        #pragma unroll
        for (int i = 0; i < 4; i++) {
            int ni = base + n0 + i;
            if (ni < NN) {
                float4 o;
                o.x = acc[i][0] + b4.x;
                o.y = acc[i][1] + b4.y;
                o.z = acc[i][2] + b4.z;
                o.w = acc[i][3] + b4.w;
                if (LAYER == 1) {
                    o.x = tanhf(o.x); o.y = tanhf(o.y);
                    o.z = tanhf(o.z); o.w = tanhf(o.w);
                }
                *reinterpret_cast<float4*>(out + (size_t)ni * DD + j0) = o;
                if (LAYER == 1) {
                    // fp16 copy for layer-2 neighbor gather
                    __half2 p0 = __floats2half2_rn(o.x, o.y);
                    __half2 p1 = __floats2half2_rn(o.z, o.w);
                    uint2 u;
                    u.x = *reinterpret_cast<unsigned int*>(&p0);
                    u.y = *reinterpret_cast<unsigned int*>(&p1);
                    *reinterpret_cast<uint2*>(g_hh + (size_t)ni * 32 + (j0 >> 1)) = u;
                }
            }
        }
    }
}

// ---------------------------------------------------------------------------
// Launch
// ---------------------------------------------------------------------------
extern "C" void kernel_launch(void* const* d_in, const int* in_sizes, int n_in,
                              void* d_out, int out_size)
{
    const float* x    = (const float*)d_in[0];
    const void*  ei   = d_in[1];
    const float* Wl1  = (const float*)d_in[2];
    const float* bl1  = (const float*)d_in[3];
    const float* Wr1  = (const float*)d_in[4];
    const float* Wl2  = (const float*)d_in[5];
    const float* bl2  = (const float*)d_in[6];
    const float* Wr2  = (const float*)d_in[7];
    float*       out  = (float*)d_out;

    // One-time immediate-API setup (capture-safe, no allocation)
    static void* deg_addr = nullptr;
    if (!deg_addr) {
        cudaGetSymbolAddress(&deg_addr, g_deg);
        cudaFuncSetAttribute(fused_kernel<1>,
            cudaFuncAttributeMaxDynamicSharedMemorySize, MLP_SMEM_BYTES);
        cudaFuncSetAttribute(fused_kernel<2>,
            cudaFuncAttributeMaxDynamicSharedMemorySize, MLP_SMEM_BYTES);
    }

    const int eb = (EE + 255) / 256;        // edge-parallel blocks
    const int hb = (NN * DD / 2 + 255) / 256;
    const int fb = 391;                     // 782 groups = 2 per block

    cudaMemsetAsync(deg_addr, 0, NN * sizeof(int));
    tohalf_kernel<<<hb, 256>>>(x);
    convert_kernel<<<eb, 256>>>(ei);
    scan_kernel<<<NB, 256>>>();
    fill_kernel<<<eb, 256>>>();
    fused_kernel<1><<<fb, 256, MLP_SMEM_BYTES>>>(x, Wl1, bl1, Wr1, nullptr);
    fused_kernel<2><<<fb, 256, MLP_SMEM_BYTES>>>(nullptr, Wl2, bl2, Wr2, out);
}

// round 14
// speedup vs baseline: 1.6879x; 1.6339x over previous
#include <cuda_runtime.h>
#include <cuda_fp16.h>
#include <cstdint>

#define NN 50000
#define EE 800000
#define DD 64
#define NB 196    // (NN + 255) / 256 scan blocks
#define PH 136    // sI/sW row pitch in halfs (272B: ldmatrix bank-conflict-free)

// Scratch (device globals — allocation-free per harness rules)
__device__ __align__(16) __half2 g_xh[NN * DD / 2]; // x as fp16 (gather + self)
__device__ __align__(16) __half2 g_hh[NN * DD / 2]; // h as fp16 (gather + self)
__device__ int g_src32[EE];
__device__ int g_dst32[EE];
__device__ int g_deg[NN];
__device__ int g_loc[NN];
__device__ int g_bsum[NB];
__device__ int g_bbase[NB];
__device__ int g_csr_src[EE];
__device__ int g_scan_count;

__device__ __forceinline__ int node_off(int n) {
    return g_loc[n] + g_bbase[n >> 8];
}

// ---------------------------------------------------------------------------
// Kernel 0: convert x -> fp16
// ---------------------------------------------------------------------------
__global__ __launch_bounds__(256) void tohalf_kernel(const float* __restrict__ x) {
    int i = blockIdx.x * 256 + threadIdx.x;
    if (i < NN * DD / 2) {
        float2 v = reinterpret_cast<const float2*>(x)[i];
        g_xh[i] = __floats2half2_rn(v.x, v.y);
    }
}

// ---------------------------------------------------------------------------
// Kernel 1: normalize indices to int32 + degree histogram (dtype self-detect)
// ---------------------------------------------------------------------------
__global__ __launch_bounds__(256) void convert_kernel(const void* __restrict__ ei) {
    const int* ei32 = (const int*)ei;
    __shared__ int s_is64;
    if (threadIdx.x == 0) s_is64 = 1;
    __syncthreads();
    if (threadIdx.x < 64 && ei32[2 * threadIdx.x + 1] != 0) atomicExch(&s_is64, 0);
    __syncthreads();

    int e = blockIdx.x * blockDim.x + threadIdx.x;
    if (e >= EE) return;
    int s, d;
    if (s_is64) {
        const long long* p = (const long long*)ei;
        s = (int)p[e];
        d = (int)p[EE + e];
    } else {
        const int* p = (const int*)ei;
        s = p[e];
        d = p[EE + e];
    }
    s = min(max(s, 0), NN - 1);
    d = min(max(d, 0), NN - 1);
    g_src32[e] = s;
    g_dst32[e] = d;
    atomicAdd(&g_deg[d], 1);
}

// ---------------------------------------------------------------------------
// Kernel 2: single-pass exclusive scan (decoupled last-block)
// ---------------------------------------------------------------------------
__global__ __launch_bounds__(256) void scan_kernel() {
    __shared__ int sh[256];
    __shared__ int is_last;
    int tid = threadIdx.x;
    int i = blockIdx.x * 256 + tid;
    int v = (i < NN) ? g_deg[i] : 0;
    sh[tid] = v;
    __syncthreads();
    #pragma unroll
    for (int d = 1; d < 256; d <<= 1) {
        int t = (tid >= d) ? sh[tid - d] : 0;
        __syncthreads();
        sh[tid] += t;
        __syncthreads();
    }
    if (i < NN) g_loc[i] = sh[tid] - v;
    if (tid == 255) g_bsum[blockIdx.x] = sh[255];

    __threadfence();
    if (tid == 0) is_last = (atomicAdd(&g_scan_count, 1) == NB - 1);
    __syncthreads();

    if (is_last) {
        int v2 = (tid < NB) ? g_bsum[tid] : 0;
        sh[tid] = v2;
        __syncthreads();
        #pragma unroll
        for (int d = 1; d < 256; d <<= 1) {
            int t = (tid >= d) ? sh[tid - d] : 0;
            __syncthreads();
            sh[tid] += t;
            __syncthreads();
        }
        if (tid < NB) g_bbase[tid] = sh[tid] - v2;
        if (tid == 0) g_scan_count = 0;
    }
}

// ---------------------------------------------------------------------------
// Kernel 3: CSR fill
// ---------------------------------------------------------------------------
__global__ __launch_bounds__(256) void fill_kernel() {
    int e = blockIdx.x * blockDim.x + threadIdx.x;
    if (e >= EE) return;
    int d = g_dst32[e];
    int off = node_off(d);
    int slot = atomicSub(&g_deg[d], 1) - 1;
    g_csr_src[off + slot] = g_src32[e];
}

// ---------------------------------------------------------------------------
// ldmatrix / mma helpers
// ---------------------------------------------------------------------------
__device__ __forceinline__ void ldsm_x4(uint32_t addr, uint32_t& a0, uint32_t& a1,
                                        uint32_t& a2, uint32_t& a3) {
    asm volatile("ldmatrix.sync.aligned.m8n8.x4.shared.b16 {%0,%1,%2,%3}, [%4];"
                 : "=r"(a0), "=r"(a1), "=r"(a2), "=r"(a3) : "r"(addr));
}
__device__ __forceinline__ void ldsm_x2(uint32_t addr, uint32_t& b0, uint32_t& b1) {
    asm volatile("ldmatrix.sync.aligned.m8n8.x2.shared.b16 {%0,%1}, [%2];"
                 : "=r"(b0), "=r"(b1) : "r"(addr));
}
__device__ __forceinline__ void mma16816(float* c, uint32_t a0, uint32_t a1,
                                         uint32_t a2, uint32_t a3,
                                         uint32_t b0, uint32_t b1) {
    asm volatile(
        "mma.sync.aligned.m16n8k16.row.col.f32.f16.f16.f32 "
        "{%0,%1,%2,%3}, {%4,%5,%6,%7}, {%8,%9}, {%0,%1,%2,%3};"
        : "+f"(c[0]), "+f"(c[1]), "+f"(c[2]), "+f"(c[3])
        : "r"(a0), "r"(a1), "r"(a2), "r"(a3), "r"(b0), "r"(b1));
}

#define ACCH(a, u) {                                            \
    __half2 _h0 = *reinterpret_cast<const __half2*>(&(u).x);    \
    __half2 _h1 = *reinterpret_cast<const __half2*>(&(u).y);    \
    float2 _f0 = __half22float2(_h0);                           \
    float2 _f1 = __half22float2(_h1);                           \
    (a).x += _f0.x; (a).y += _f0.y; (a).z += _f1.x; (a).w += _f1.y; }

// ---------------------------------------------------------------------------
// Kernel 4/5: FUSED aggregation + tensor-core MLP.
// One 64-node group per block, 256 threads, static smem ~35KB (6 blocks/SM).
// Gather (R13 path): half-warp per node, fp16 rows -> fp32 acc -> fp16 sI.
// Compute: mma.sync m16n8k16; warp (wid%4 -> 16-node tile, wid/4 -> 32 j).
// sI[node][k] fp16 pitch PH; sW[j][k] fp16 pitch PH (row.col mma layout).
// Layer 1 writes only g_hh (fp16); layer 2 writes fp32 d_out.
// ---------------------------------------------------------------------------
template <int LAYER>
__global__ __launch_bounds__(256) void fused_kernel(
    const float* __restrict__ Wl,
    const float* __restrict__ bl,
    const float* __restrict__ Wr,
    float* __restrict__ outext)
{
    const __half2* nb = (LAYER == 1) ? g_xh : g_hh;   // fp16 rows (neighbors+self)

    __shared__ __half sI[64 * PH];
    __shared__ __half sW[64 * PH];
    __shared__ float  sB[DD];

    // Stage combined weights [j][k0..127] as fp16
    for (int t = threadIdx.x; t < 64 * 128; t += 256) {
        int j = t >> 7, kk = t & 127;
        float v = (kk < 64) ? Wl[(j << 6) + kk] : Wr[(j << 6) + kk - 64];
        sW[j * PH + kk] = __float2half_rn(v);
    }
    if (threadIdx.x < DD) sB[threadIdx.x] = bl[threadIdx.x];

    const int wid  = threadIdx.x >> 5;      // warp 0..7
    const int lane = threadIdx.x & 31;
    const int half = lane >> 4;             // 0/1
    const int fl   = lane & 15;             // feature float4 index
    const int fo   = fl << 2;               // feature offset (floats/halfs)

    const int base = blockIdx.x << 6;       // 782 blocks cover 50048 nodes

    // ---- Gather + stage: half-warp owns 4 nodes, processed as 2 pairs ----
    #pragma unroll 1
    for (int pp = 0; pp < 2; pp++) {
        int nodeA = (wid << 3) + (pp << 2) + half;  // 0..63
        int nodeB = nodeA + 2;
        int niA = base + nodeA;
        int niB = base + nodeB;
        int begA = 0, lenA = 0, begB = 0, lenB = 0;
        if (niA < NN) {
            begA = node_off(niA);
            lenA = ((niA + 1 < NN) ? node_off(niA + 1) : EE) - begA;
        }
        if (niB < NN) {
            begB = node_off(niB);
            lenB = ((niB + 1 < NN) ? node_off(niB + 1) : EE) - begB;
        }

        float4 aA0 = make_float4(0.f, 0.f, 0.f, 0.f);
        float4 aA1 = make_float4(0.f, 0.f, 0.f, 0.f);
        float4 aB0 = make_float4(0.f, 0.f, 0.f, 0.f);
        float4 aB1 = make_float4(0.f, 0.f, 0.f, 0.f);

        int m = max(lenA, lenB);
        #pragma unroll 1
        for (int i = 0; i < m; i += 2) {
            int sA0 = (i     < lenA) ? g_csr_src[begA + i]     : -1;
            int sA1 = (i + 1 < lenA) ? g_csr_src[begA + i + 1] : -1;
            int sB0 = (i     < lenB) ? g_csr_src[begB + i]     : -1;
            int sB1 = (i + 1 < lenB) ? g_csr_src[begB + i + 1] : -1;
            if (sA0 >= 0) { uint2 u = reinterpret_cast<const uint2*>(nb + (size_t)sA0 * 32)[fl]; ACCH(aA0, u); }
            if (sA1 >= 0) { uint2 u = reinterpret_cast<const uint2*>(nb + (size_t)sA1 * 32)[fl]; ACCH(aA1, u); }
            if (sB0 >= 0) { uint2 u = reinterpret_cast<const uint2*>(nb + (size_t)sB0 * 32)[fl]; ACCH(aB0, u); }
            if (sB1 >= 0) { uint2 u = reinterpret_cast<const uint2*>(nb + (size_t)sB1 * 32)[fl]; ACCH(aB1, u); }
        }

        float invA = 1.0f / (float)max(lenA, 1);
        float invB = 1.0f / (float)max(lenB, 1);
        {
            __half2 p0 = __floats2half2_rn((aA0.x + aA1.x) * invA, (aA0.y + aA1.y) * invA);
            __half2 p1 = __floats2half2_rn((aA0.z + aA1.z) * invA, (aA0.w + aA1.w) * invA);
            uint2 u; u.x = *reinterpret_cast<uint32_t*>(&p0); u.y = *reinterpret_cast<uint32_t*>(&p1);
            *reinterpret_cast<uint2*>(&sI[nodeA * PH + fo]) = u;
        }
        {
            __half2 p0 = __floats2half2_rn((aB0.x + aB1.x) * invB, (aB0.y + aB1.y) * invB);
            __half2 p1 = __floats2half2_rn((aB0.z + aB1.z) * invB, (aB0.w + aB1.w) * invB);
            uint2 u; u.x = *reinterpret_cast<uint32_t*>(&p0); u.y = *reinterpret_cast<uint32_t*>(&p1);
            *reinterpret_cast<uint2*>(&sI[nodeB * PH + fo]) = u;
        }

        // Self rows (fp16, direct copy)
        uint2 uA = make_uint2(0u, 0u), uB = make_uint2(0u, 0u);
        if (niA < NN) uA = reinterpret_cast<const uint2*>(nb + (size_t)niA * 32)[fl];
        if (niB < NN) uB = reinterpret_cast<const uint2*>(nb + (size_t)niB * 32)[fl];
        *reinterpret_cast<uint2*>(&sI[nodeA * PH + DD + fo]) = uA;
        *reinterpret_cast<uint2*>(&sI[nodeB * PH + DD + fo]) = uB;
    }
    __syncthreads();

    // ---- Compute: tensor cores. Warp tile: 16 nodes x 32 j ----
    const int mw = (wid & 3) << 4;          // 0,16,32,48
    const int jw = (wid >> 2) << 5;         // 0 or 32

    float c[4][4];
    #pragma unroll
    for (int js = 0; js < 4; js++)
        #pragma unroll
        for (int q = 0; q < 4; q++) c[js][q] = 0.f;

    uint32_t siBase = (uint32_t)__cvta_generic_to_shared(sI);
    uint32_t swBase = (uint32_t)__cvta_generic_to_shared(sW);
    const int rA = lane & 15, cbA = lane >> 4;
    const int rB = lane & 7,  kbB = (lane >> 3) & 1;

    #pragma unroll
    for (int ks = 0; ks < 8; ks++) {
        int k0 = ks << 4;
        uint32_t a0, a1, a2, a3;
        ldsm_x4(siBase + (uint32_t)(((mw + rA) * PH + k0 + cbA * 8) * 2), a0, a1, a2, a3);
        #pragma unroll
        for (int js = 0; js < 4; js++) {
            uint32_t b0, b1;
            ldsm_x2(swBase + (uint32_t)(((jw + (js << 3) + rB) * PH + k0 + kbB * 8) * 2), b0, b1);
            mma16816(c[js], a0, a1, a2, a3, b0, b1);
        }
    }

    // ---- Epilogue ----
    // D frag: {c0,c1} -> row lane/4,   cols cc, cc+1
    //         {c2,c3} -> row lane/4+8, cols cc, cc+1
    const int r1 = mw + (lane >> 2);
    const int r2 = r1 + 8;
    const int cc = (lane & 3) << 1;
    const int ni1 = base + r1;
    const int ni2 = base + r2;

    #pragma unroll
    for (int js = 0; js < 4; js++) {
        int j = jw + (js << 3) + cc;
        float bx = sB[j], by = sB[j + 1];
        float v0 = c[js][0] + bx, v1 = c[js][1] + by;   // row r1
        float v2 = c[js][2] + bx, v3 = c[js][3] + by;   // row r2
        if (LAYER == 1) {
            v0 = tanhf(v0); v1 = tanhf(v1);
            v2 = tanhf(v2); v3 = tanhf(v3);
            if (ni1 < NN) g_hh[(size_t)ni1 * 32 + (j >> 1)] = __floats2half2_rn(v0, v1);
            if (ni2 < NN) g_hh[(size_t)ni2 * 32 + (j >> 1)] = __floats2half2_rn(v2, v3);
        } else {
            if (ni1 < NN) *reinterpret_cast<float2*>(outext + (size_t)ni1 * DD + j) = make_float2(v0, v1);
            if (ni2 < NN) *reinterpret_cast<float2*>(outext + (size_t)ni2 * DD + j) = make_float2(v2, v3);
        }
    }
}

// ---------------------------------------------------------------------------
// Launch
// ---------------------------------------------------------------------------
extern "C" void kernel_launch(void* const* d_in, const int* in_sizes, int n_in,
                              void* d_out, int out_size)
{
    const float* x    = (const float*)d_in[0];
    const void*  ei   = d_in[1];
    const float* Wl1  = (const float*)d_in[2];
    const float* bl1  = (const float*)d_in[3];
    const float* Wr1  = (const float*)d_in[4];
    const float* Wl2  = (const float*)d_in[5];
    const float* bl2  = (const float*)d_in[6];
    const float* Wr2  = (const float*)d_in[7];
    float*       out  = (float*)d_out;

    static void* deg_addr = nullptr;
    if (!deg_addr) cudaGetSymbolAddress(&deg_addr, g_deg);

    const int eb = (EE + 255) / 256;
    const int hb = (NN * DD / 2 + 255) / 256;
    const int fb = (NN + 63) / 64;          // 782 blocks, one 64-node group each

    cudaMemsetAsync(deg_addr, 0, NN * sizeof(int));
    tohalf_kernel<<<hb, 256>>>(x);
    convert_kernel<<<eb, 256>>>(ei);
    scan_kernel<<<NB, 256>>>();
    fill_kernel<<<eb, 256>>>();
    fused_kernel<1><<<fb, 256>>>(Wl1, bl1, Wr1, nullptr);
    fused_kernel<2><<<fb, 256>>>(Wl2, bl2, Wr2, out);
}